// round 5
// baseline (speedup 1.0000x reference)
#include <cuda_runtime.h>
#include <cuda_bf16.h>
#include <math_constants.h>

#define E  512
#define L  1024
#define B2 512

__device__ float g_v[E];
__device__ float g_c;
__device__ float g_partial[128 * E];   // prep stage-A partials
__device__ int   g_next;               // dynamic row queue head

// ---------------------------------------------------------------------------
// Prep stage A: 128 blocks x 512 threads. Block j reduces W rows [4j, 4j+4);
// thread t owns column e = t (scalar, coalesced). Also resets the row queue.
// ---------------------------------------------------------------------------
__global__ __launch_bounds__(512)
void prep_partial(const float* __restrict__ W,
                  const float* __restrict__ wv) {
    const int j = blockIdx.x;           // 0..127
    const int e = threadIdx.x;          // 0..511
    const int f0 = j * 4;

    if (j == 0 && e == 0) g_next = 0;   // reset queue for this launch

    float acc = 0.f;
    #pragma unroll
    for (int r = 0; r < 4; ++r)
        acc = fmaf(__ldg(W + (size_t)(f0 + r) * E + e), __ldg(wv + f0 + r), acc);
    g_partial[(size_t)j * E + e] = acc;
}

// ---------------------------------------------------------------------------
// Prep stage B: fold 128 partials into g_v; block 0 computes c = bias . wv.
// ---------------------------------------------------------------------------
__global__ __launch_bounds__(128)
void prep_reduce(const float* __restrict__ bias,
                 const float* __restrict__ wv) {
    __shared__ float s_red[4];
    const int t = threadIdx.x;
    const int e = blockIdx.x * 128 + t;

    float s = 0.f;
    #pragma unroll 16
    for (int j = 0; j < 128; ++j)
        s += g_partial[j * E + e];
    g_v[e] = s;

    if (blockIdx.x == 0) {
        const int warp = t >> 5, lane = t & 31;
        float part = 0.f;
        #pragma unroll
        for (int f = t; f < E; f += 128)
            part = fmaf(__ldg(bias + f), __ldg(wv + f), part);
        #pragma unroll
        for (int o = 16; o; o >>= 1)
            part += __shfl_down_sync(0xffffffffu, part, o);
        if (lane == 0) s_red[warp] = part;
        __syncthreads();
        if (t == 0)
            g_c = s_red[0] + s_red[1] + s_red[2] + s_red[3];
    }
}

// ---------------------------------------------------------------------------
// Persistent fused attention: CTAs pop rows off a global queue; per row,
// warp-per-token scores into smem, block softmax, write out. No global
// score round-trip, no fences.
// ---------------------------------------------------------------------------
#define NBLOCKS 304   // 2 CTAs per SM (152 SMs on GB300)

__global__ __launch_bounds__(1024, 2)
void attn_persistent(const float* __restrict__ q,
                     const int* __restrict__ lens,
                     float* __restrict__ out) {
    __shared__ float s_v[E];
    __shared__ float s_scores[L];
    __shared__ float s_red[32];
    __shared__ float s_bcast;
    __shared__ int   s_row;

    const int tid  = threadIdx.x;
    const int warp = tid >> 5;
    const int lane = tid & 31;

    if (tid < E) s_v[tid] = g_v[tid];
    const float c = g_c;
    const float4* __restrict__ vv = reinterpret_cast<const float4*>(s_v);

    for (;;) {
        if (tid == 0) s_row = atomicAdd(&g_next, 1);
        __syncthreads();                      // s_v ready (first iter) + s_row
        const int b = s_row;
        if (b >= B2) break;
        const int len = lens[b];
        const float* __restrict__ qrow = q + (size_t)b * L * E;

        // ---- scores: one warp per token ----
        for (int l = warp; l < len; l += 32) {
            const float4* __restrict__ qp =
                reinterpret_cast<const float4*>(qrow + (size_t)l * E);
            float acc = 0.f;
            #pragma unroll
            for (int k = 0; k < 4; ++k) {
                float4 a = __ldg(qp + k * 32 + lane);
                float4 w = vv[k * 32 + lane];
                acc = fmaf(a.x, w.x, acc);
                acc = fmaf(a.y, w.y, acc);
                acc = fmaf(a.z, w.z, acc);
                acc = fmaf(a.w, w.w, acc);
            }
            #pragma unroll
            for (int o = 16; o; o >>= 1)
                acc += __shfl_down_sync(0xffffffffu, acc, o);
            if (lane == 0) s_scores[l] = acc + c;
        }
        __syncthreads();

        // ---- softmax over [0, len) ----
        float val = (tid < len) ? s_scores[tid] : -CUDART_INF_F;

        float m = val;
        #pragma unroll
        for (int o = 16; o; o >>= 1)
            m = fmaxf(m, __shfl_down_sync(0xffffffffu, m, o));
        if (lane == 0) s_red[warp] = m;
        __syncthreads();
        if (warp == 0) {
            float t = s_red[lane];
            #pragma unroll
            for (int o = 16; o; o >>= 1)
                t = fmaxf(t, __shfl_down_sync(0xffffffffu, t, o));
            if (lane == 0) s_bcast = t;
        }
        __syncthreads();
        const float rowmax = s_bcast;

        float ex = (tid < len) ? __expf(val - rowmax) : 0.f;

        float s = ex;
        #pragma unroll
        for (int o = 16; o; o >>= 1)
            s += __shfl_down_sync(0xffffffffu, s, o);
        __syncthreads();                      // s_red reuse
        if (lane == 0) s_red[warp] = s;
        __syncthreads();
        if (warp == 0) {
            float t = s_red[lane];
            #pragma unroll
            for (int o = 16; o; o >>= 1)
                t += __shfl_down_sync(0xffffffffu, t, o);
            if (lane == 0) s_bcast = t;
        }
        __syncthreads();

        out[(size_t)b * L + tid] = ex / s_bcast;
        __syncthreads();                      // protect s_scores/s_red reuse
    }
}

extern "C" void kernel_launch(void* const* d_in, const int* in_sizes, int n_in,
                              void* d_out, int out_size) {
    const float* questions = (const float*)d_in[0];   // [B2, L, E]
    const int*   lens      = (const int*)d_in[1];     // [B2]
    const float* W         = (const float*)d_in[2];   // [E, E]
    const float* bias      = (const float*)d_in[3];   // [E]
    const float* wv        = (const float*)d_in[4];   // [E, 1]
    float* out             = (float*)d_out;           // [B2, L]

    prep_partial<<<128, 512>>>(W, wv);
    prep_reduce<<<4, 128>>>(bias, wv);
    attn_persistent<<<NBLOCKS, 1024>>>(questions, lens, out);
}

// round 6
// speedup vs baseline: 1.1948x; 1.1948x over previous
#include <cuda_runtime.h>
#include <cuda_bf16.h>
#include <math_constants.h>

#define E  512
#define L  1024
#define B2 512
#define CHUNK 128

__device__ float g_v[E];
__device__ float g_c;
__device__ float g_scores[B2 * L];     // raw attention energies
__device__ float g_partial[128 * E];   // prep stage-A partials

// ---------------------------------------------------------------------------
// Prep stage A: 128 blocks x 512 threads. Block j reduces W rows [4j, 4j+4);
// thread t owns column e = t (scalar, coalesced).
// ---------------------------------------------------------------------------
__global__ __launch_bounds__(512)
void prep_partial(const float* __restrict__ W,
                  const float* __restrict__ wv) {
    const int j = blockIdx.x;           // 0..127
    const int e = threadIdx.x;          // 0..511
    const int f0 = j * 4;

    float acc = 0.f;
    #pragma unroll
    for (int r = 0; r < 4; ++r)
        acc = fmaf(__ldg(W + (size_t)(f0 + r) * E + e), __ldg(wv + f0 + r), acc);
    g_partial[(size_t)j * E + e] = acc;
}

// ---------------------------------------------------------------------------
// Prep stage B: fold 128 partials into g_v; block 0 computes c = bias . wv.
// ---------------------------------------------------------------------------
__global__ __launch_bounds__(128)
void prep_reduce(const float* __restrict__ bias,
                 const float* __restrict__ wv) {
    __shared__ float s_red[4];
    const int t = threadIdx.x;
    const int e = blockIdx.x * 128 + t;

    float s = 0.f;
    #pragma unroll 16
    for (int j = 0; j < 128; ++j)
        s += g_partial[j * E + e];
    g_v[e] = s;

    if (blockIdx.x == 0) {
        const int warp = t >> 5, lane = t & 31;
        float part = 0.f;
        #pragma unroll
        for (int f = t; f < E; f += 128)
            part = fmaf(__ldg(bias + f), __ldg(wv + f), part);
        #pragma unroll
        for (int o = 16; o; o >>= 1)
            part += __shfl_down_sync(0xffffffffu, part, o);
        if (lane == 0) s_red[warp] = part;
        __syncthreads();
        if (t == 0)
            g_c = s_red[0] + s_red[1] + s_red[2] + s_red[3];
    }
}

// ---------------------------------------------------------------------------
// Scores: grid (L/CHUNK, B2), 256 threads = 8 warps, 16 tokens per warp.
// R2-proven inner loop, light unroll for load/shuffle overlap.
// ---------------------------------------------------------------------------
__global__ __launch_bounds__(256)
void scores_kernel(const float* __restrict__ q,
                   const int* __restrict__ lens) {
    __shared__ float s_v[E];

    const int tid  = threadIdx.x;
    const int warp = tid >> 5;
    const int lane = tid & 31;
    const int b    = blockIdx.y;
    const int base = blockIdx.x * CHUNK;
    const int len  = lens[b];

    if (base >= len) return;                 // whole chunk masked out

    #pragma unroll
    for (int i = tid; i < E; i += 256) s_v[i] = g_v[i];
    __syncthreads();

    const float c = g_c;
    const float4* __restrict__ vv = reinterpret_cast<const float4*>(s_v);
    const float*  __restrict__ qrow = q + (size_t)b * L * E;
    const int tok_end = min(base + CHUNK, len);

    #pragma unroll 2
    for (int l = base + warp * 16; l < min(base + warp * 16 + 16, tok_end); ++l) {
        const float4* __restrict__ qp =
            reinterpret_cast<const float4*>(qrow + (size_t)l * E);
        float acc = 0.f;
        #pragma unroll
        for (int k = 0; k < 4; ++k) {
            float4 a = __ldg(qp + k * 32 + lane);
            float4 w = vv[k * 32 + lane];
            acc = fmaf(a.x, w.x, acc);
            acc = fmaf(a.y, w.y, acc);
            acc = fmaf(a.z, w.z, acc);
            acc = fmaf(a.w, w.w, acc);
        }
        #pragma unroll
        for (int o = 16; o; o >>= 1)
            acc += __shfl_down_sync(0xffffffffu, acc, o);
        if (lane == 0) g_scores[b * L + l] = acc + c;
    }
}

// ---------------------------------------------------------------------------
// Softmax over valid prefix. One block of 256 per row; float4 I/O,
// 4 elements per thread, two compact reduce stages.
// ---------------------------------------------------------------------------
__global__ __launch_bounds__(256)
void softmax_kernel(const int* __restrict__ lens,
                    float* __restrict__ out) {
    __shared__ float s_red[8];
    __shared__ float s_bcast;

    const int tid  = threadIdx.x;
    const int warp = tid >> 5;
    const int lane = tid & 31;
    const int b    = blockIdx.x;
    const int len  = lens[b];
    const int i0   = tid * 4;

    float4 sc = *reinterpret_cast<const float4*>(g_scores + b * L + i0);
    float x0 = (i0 + 0 < len) ? sc.x : -CUDART_INF_F;
    float x1 = (i0 + 1 < len) ? sc.y : -CUDART_INF_F;
    float x2 = (i0 + 2 < len) ? sc.z : -CUDART_INF_F;
    float x3 = (i0 + 3 < len) ? sc.w : -CUDART_INF_F;

    float m = fmaxf(fmaxf(x0, x1), fmaxf(x2, x3));
    #pragma unroll
    for (int o = 16; o; o >>= 1)
        m = fmaxf(m, __shfl_down_sync(0xffffffffu, m, o));
    if (lane == 0) s_red[warp] = m;
    __syncthreads();
    if (warp == 0) {
        float t = (lane < 8) ? s_red[lane] : -CUDART_INF_F;
        #pragma unroll
        for (int o = 4; o; o >>= 1)
            t = fmaxf(t, __shfl_down_sync(0xffffffffu, t, o));
        if (lane == 0) s_bcast = t;
    }
    __syncthreads();
    const float rowmax = s_bcast;

    float e0 = (i0 + 0 < len) ? __expf(x0 - rowmax) : 0.f;
    float e1 = (i0 + 1 < len) ? __expf(x1 - rowmax) : 0.f;
    float e2 = (i0 + 2 < len) ? __expf(x2 - rowmax) : 0.f;
    float e3 = (i0 + 3 < len) ? __expf(x3 - rowmax) : 0.f;

    float s = e0 + e1 + e2 + e3;
    #pragma unroll
    for (int o = 16; o; o >>= 1)
        s += __shfl_down_sync(0xffffffffu, s, o);
    __syncthreads();
    if (lane == 0) s_red[warp] = s;
    __syncthreads();
    if (warp == 0) {
        float t = (lane < 8) ? s_red[lane] : 0.f;
        #pragma unroll
        for (int o = 4; o; o >>= 1)
            t += __shfl_down_sync(0xffffffffu, t, o);
        if (lane == 0) s_bcast = t;
    }
    __syncthreads();
    const float inv = 1.f / s_bcast;

    float4 r = make_float4(e0 * inv, e1 * inv, e2 * inv, e3 * inv);
    *reinterpret_cast<float4*>(out + (size_t)b * L + i0) = r;
}

extern "C" void kernel_launch(void* const* d_in, const int* in_sizes, int n_in,
                              void* d_out, int out_size) {
    const float* questions = (const float*)d_in[0];   // [B2, L, E]
    const int*   lens      = (const int*)d_in[1];     // [B2]
    const float* W         = (const float*)d_in[2];   // [E, E]
    const float* bias      = (const float*)d_in[3];   // [E]
    const float* wv        = (const float*)d_in[4];   // [E, 1]
    float* out             = (float*)d_out;           // [B2, L]

    prep_partial<<<128, 512>>>(W, wv);
    prep_reduce<<<4, 128>>>(bias, wv);
    dim3 sgrid(L / CHUNK, B2);
    scores_kernel<<<sgrid, 256>>>(questions, lens);
    softmax_kernel<<<B2, 256>>>(lens, out);
}